// round 8
// baseline (speedup 1.0000x reference)
#include <cuda_runtime.h>

// KSpaceMap, fused single kernel.
//   A[b,h,i] = sum_w x[b,h,w] e^{-j*2pi*i*w/128}   (row DFT; the ifft along H
//              cancels the H-axis part of fft2)
//   out[b,i,h,w] = (Ar[b,h,i]*cos(th) - Ai[b,h,i]*sin(th))/128, th = 2pi*i*w/128
// Symmetry: out[b,128-i] == out[b,i]  (real input => conjugate-symmetric DFT,
// and cos/sin mirror). So only i = 0..64 are computed; i = 1..63 store twice.
// mask input is unused by the reference.

#define NW 128
#define NI 65                     // distinct frequency planes
#define TWO_PI 6.28318530717958647692f

// One rotation step + accumulate for one x component.
#define STEP(XC)                                            \
    do {                                                    \
        car = fmaf((XC), zr, car);                          \
        sai = fmaf((XC), zi, sai);                          \
        float nzr = fmaf(zr, ur, -zi * ui);                 \
        float nzi = fmaf(zr, ui,  zi * ur);                 \
        zr = nzr; zi = nzi;                                 \
    } while (0)

__global__ void __launch_bounds__(256) kspace_fused(const float* __restrict__ x,
                                                    float4* __restrict__ out) {
    __shared__ float sCar[NW];    // sum x*cos  per h
    __shared__ float sSai[NW];    // sum x*sin  per h
    __shared__ float sc[NW];      // cos(2pi*i*w/128)/128
    __shared__ float ss[NW];      // sin(2pi*i*w/128)/128

    const int bid = blockIdx.x;   // b*65 + i
    const int b   = bid / NI;
    const int i   = bid - b * NI; // 0..64
    const int tid = threadIdx.x;

    // ---- Phase-B twiddle tables (exact: reduce i*w mod 128 first) ----
    if (tid < NW) {
        const int t = (i * tid) & (NW - 1);
        float s, c;
        sincosf(TWO_PI * (float)t * (1.0f / (float)NW), &s, &c);
        sc[tid] = c * (1.0f / (float)NW);
        ss[tid] = s * (1.0f / (float)NW);
    }

    // ---- Phase A: DFT coefficient A[b,h,i] for all h (2 threads per row) ----
    const int h    = tid >> 1;
    const int half = tid & 1;
    const int w0   = half << 6;   // 0 or 64
    const float4* __restrict__ xrow =
        (const float4*)(x + ((size_t)b * NW + h) * NW + w0);

    // step twiddle u = e^{+j*2pi*i/128} applied to z accumulating (cos, sin)
    float ur, ui;
    sincosf(TWO_PI * (float)i * (1.0f / (float)NW), &ui, &ur);
    float zr, zi;
    {
        const int t0 = (i * w0) & (NW - 1);
        sincosf(TWO_PI * (float)t0 * (1.0f / (float)NW), &zi, &zr);
    }

    float car = 0.0f, sai = 0.0f;
#pragma unroll
    for (int j = 0; j < 16; ++j) {
        const float4 xv = xrow[j];
        STEP(xv.x);
        STEP(xv.y);
        STEP(xv.z);
        STEP(xv.w);
    }
    // combine the two half-row partial sums (lanes t and t^1 share h)
    car += __shfl_xor_sync(0xffffffffu, car, 1);
    sai += __shfl_xor_sync(0xffffffffu, sai, 1);
    if (!half) { sCar[h] = car; sSai[h] = sai; }
    __syncthreads();

    // ---- Phase B: store-bound expansion, plane i and mirror plane 128-i ----
    // out[b,i,h,w] = car*cos/W + sai*sin/W   (since Ai = -sai)
    const int w4 = tid & 31;      // float4 column group
    const int h0 = tid >> 5;      // 0..7

    const float c0 = sc[4 * w4 + 0], c1 = sc[4 * w4 + 1];
    const float c2 = sc[4 * w4 + 2], c3 = sc[4 * w4 + 3];
    const float s0 = ss[4 * w4 + 0], s1 = ss[4 * w4 + 1];
    const float s2 = ss[4 * w4 + 2], s3 = ss[4 * w4 + 3];

    const size_t plane = (size_t)NW * (NW / 4);   // float4s per i-plane
    float4* __restrict__ o1 = out + ((size_t)b * NW + i) * plane + w4;
    float4* __restrict__ o2 = out + ((size_t)b * NW + (NW - i)) * plane + w4;
    const bool dup = (i >= 1) && (i <= 63);

#pragma unroll
    for (int hh = h0; hh < NW; hh += 8) {
        const float ar = sCar[hh];
        const float ai = sSai[hh];
        float4 o;
        o.x = fmaf(ar, c0, ai * s0);
        o.y = fmaf(ar, c1, ai * s1);
        o.z = fmaf(ar, c2, ai * s2);
        o.w = fmaf(ar, c3, ai * s3);
        o1[(size_t)hh * (NW / 4)] = o;
        if (dup) o2[(size_t)hh * (NW / 4)] = o;
    }
}

extern "C" void kernel_launch(void* const* d_in, const int* in_sizes, int n_in,
                              void* d_out, int out_size) {
    // input (32,1,128,128) = 524288 elems; mask (32,1,1,128) unused.
    const float* x = (const float*)d_in[0];
    if (in_sizes[0] != 32 * NW * NW && n_in > 1) {
        x = (const float*)d_in[1];
    }
    kspace_fused<<<32 * NI, 256>>>(x, (float4*)d_out);
}